// round 8
// baseline (speedup 1.0000x reference)
#include <cuda_runtime.h>
#include <math.h>
#include <stdint.h>

#define B_ 64
#define A_ 8732
#define G_ 50
#define C_ 81

// ---- K1: block-per-batch strips; warp-private 4-deep cp.async pipelines ----
#define TILE4 4
#define NTB 2183                        // 8732/4 exactly -> all tiles full
#define SPB 11                          // strips per batch -> 704 blocks (1 wave @5/SM)
#define TPS 199                         // ceil(2183/11)
#define WPB 8                           // warps per block
#define K1T (WPB * 32)                  // 256
#define NBUF 4
#define ROWF (TILE4 * C_)               // 324 floats (1296 B) per tile buffer

// ---- K2 config ----
#define K2T 1024
#define NWARP (K2T / 32)

// Scratch (no device alloc allowed).
//   negative anchor: v = conf >= 0
//   positive anchor: v = -(sl1 + conf) - 2  (<= -2, disjoint)
__device__ float g_work[B_ * A_];
__device__ float g_batch_loss[B_];
__device__ int   g_batch_np[B_];
__device__ int   g_ticket = 0;

__device__ __forceinline__ float fast_ex2(float x)
{
    float r;
    asm("ex2.approx.ftz.f32 %0, %1;" : "=f"(r) : "f"(x));
    return r;
}
__device__ __forceinline__ uint32_t smem_u32(const void* p)
{
    uint32_t a;
    asm("{ .reg .u64 t; cvta.to.shared.u64 t, %1; cvt.u32.u64 %0, t; }" : "=r"(a) : "l"(p));
    return a;
}
__device__ __forceinline__ void cp16(uint32_t dst, const void* src)
{
    asm volatile("cp.async.cg.shared.global [%0], [%1], 16;" :: "r"(dst), "l"(src));
}

// ---------------------------------------------------------------------------
// K1: blockIdx.y = batch, blockIdx.x = strip. GT boxes/areas/labels staged
// once per block. Each warp owns a 4-deep cp.async pipeline of 4-anchor tiles
// (depth 3 in flight hides full DRAM latency). Eight lanes serve one anchor:
// octant o splits the 50 GTs (7,7,6,6,6,6,6,6) and 81 classes (11,10x7);
// partials merged via three shfl_xor levels.
// ---------------------------------------------------------------------------
__global__ void __launch_bounds__(K1T, 5) k1_anchor(
    const float4* __restrict__ pred_boxes,   // [B, A, 4]
    const float*  __restrict__ pred_scores,  // [B, A, C]
    const float4* __restrict__ gt_boxes,     // [B, G, 4]
    const int*    __restrict__ gt_labels)    // [B, G]
{
    __shared__ __align__(16) float  sbuf[WPB][NBUF][ROWF];   // 41472 B
    __shared__ __align__(16) float4 s_gtb[G_];
    __shared__ float s_gta[G_];
    __shared__ int   s_gl[G_];

    const int tid  = threadIdx.x;
    const int lane = tid & 31;
    const int wid  = tid >> 5;
    const int al   = lane & 3;      // anchor slot in tile
    const int o    = lane >> 2;     // octant 0..7

    const int b = blockIdx.y;

    if (tid < G_) {
        float4 g = gt_boxes[b * G_ + tid];
        s_gtb[tid] = g;
        s_gta[tid] = (g.z - g.x) * (g.w - g.y);
        s_gl[tid]  = gt_labels[b * G_ + tid];
    }
    __syncthreads();

    const int gbase = (o < 2) ? o * 7 : 14 + (o - 2) * 6;   // 0,7,14,20,26,32,38,44
    const int gext  = (o < 2);                              // 7th GT
    const int cbase = (o == 0) ? 0 : 11 + (o - 1) * 10;     // 0,11,21,...,71
    const int cext  = (o == 0);                             // 11th class

    const int strip_lo = blockIdx.x * TPS;
    const int strip_hi = min(strip_lo + TPS, NTB);

    const uint32_t buf0 = smem_u32(&sbuf[wid][0][0]);
    const float L2E = 1.4426950408889634f;
    const float* sc_base = pred_scores + (size_t)b * A_ * C_;

    auto prefetch = [&](int ti, int sel) {
        const float4* src = (const float4*)(sc_base + (size_t)ti * (TILE4 * C_));
        const uint32_t dst = buf0 + sel * (ROWF * 4);
        #pragma unroll
        for (int i = 0; i < 3; i++) {
            int idx = lane + i * 32;
            if (idx < ROWF / 4) cp16(dst + idx * 16, src + idx);
        }
    };

    const int t0 = strip_lo + wid;
    // prologue: fill 3 pipeline stages
    #pragma unroll
    for (int j = 0; j < NBUF - 1; j++) {
        int tp = t0 + j * WPB;
        if (tp < strip_hi) prefetch(tp, j);
        asm volatile("cp.async.commit_group;");
    }

    int cnt = 0;
    for (int ti = t0; ti < strip_hi; ti += WPB, cnt++) {
        const int a0 = ti * TILE4;
        const int anchor = a0 + al;

        // anchor box load overlaps the pipeline wait
        const float4 pb = __ldg(pred_boxes + (size_t)b * A_ + anchor);

        const int tp = ti + (NBUF - 1) * WPB;
        if (tp < strip_hi) prefetch(tp, (cnt + NBUF - 1) & (NBUF - 1));
        asm volatile("cp.async.commit_group;");
        asm volatile("cp.async.wait_group 3;");   // current tile's group done
        __syncwarp();

        const float area_a = (pb.z - pb.x) * (pb.w - pb.y);

        // ---- IoU argmax over this octant's 6-7 GTs (division-free) ----
        float bi = -1.0f, bu = 1.0f;
        int bidx = gbase;
        #pragma unroll
        for (int g = 0; g < 6; g++) {
            float4 gb = s_gtb[gbase + g];
            float iw = fmaxf(fminf(pb.z, gb.z) - fmaxf(pb.x, gb.x), 0.0f);
            float ih = fminf(pb.w, gb.w) - fmaxf(pb.y, gb.y);
            float inter = iw * ih;
            float un = (area_a + s_gta[gbase + g]) - inter;   // > 0 always
            if (inter * bu > bi * un) { bi = inter; bu = un; bidx = gbase + g; }
        }
        if (gext) {
            float4 gb = s_gtb[gbase + 6];
            float iw = fmaxf(fminf(pb.z, gb.z) - fmaxf(pb.x, gb.x), 0.0f);
            float ih = fminf(pb.w, gb.w) - fmaxf(pb.y, gb.y);
            float inter = iw * ih;
            float un = (area_a + s_gta[gbase + 6]) - inter;
            if (inter * bu > bi * un) { bi = inter; bu = un; bidx = gbase + 6; }
        }
        // merge octants (lower index wins ties -> argmax-first semantics)
        #pragma unroll
        for (int off = 4; off <= 16; off <<= 1) {
            float obi = __shfl_xor_sync(0xffffffffu, bi, off);
            float obu = __shfl_xor_sync(0xffffffffu, bu, off);
            int   obx = __shfl_xor_sync(0xffffffffu, bidx, off);
            float lhs = obi * bu, rhs = bi * obu;
            if (lhs > rhs || (lhs == rhs && obx < bidx)) { bi = obi; bu = obu; bidx = obx; }
        }
        const bool pos = bi > 0.5f * bu;
        const int  tl  = pos ? s_gl[bidx] : 0;

        // ---- softmax octant: 10(+1) classes from this warp's smem tile ----
        const float* row = &sbuf[wid][cnt & (NBUF - 1)][al * C_];
        float s0 = 0.0f, s1 = 0.0f;
        #pragma unroll
        for (int j = 0; j < 10; j += 2) {
            s0 += fast_ex2(row[cbase + j]     * L2E);
            s1 += fast_ex2(row[cbase + j + 1] * L2E);
        }
        float s = s0 + s1;
        if (cext) s += fast_ex2(row[10] * L2E);
        s += __shfl_xor_sync(0xffffffffu, s, 4);
        s += __shfl_xor_sync(0xffffffffu, s, 8);
        s += __shfl_xor_sync(0xffffffffu, s, 16);
        const float conf = __logf(s) - row[tl];

        // ---- emit (octant 0 only; all 4 anchors valid) ----
        if (o == 0) {
            float outv;
            if (tl > 0) {
                float4 gb = s_gtb[bidx];
                float sl1 = 0.0f, d, ad;
                d = pb.x - gb.x; ad = fabsf(d); sl1 += (ad < 1.0f) ? 0.5f * d * d : ad - 0.5f;
                d = pb.y - gb.y; ad = fabsf(d); sl1 += (ad < 1.0f) ? 0.5f * d * d : ad - 0.5f;
                d = pb.z - gb.z; ad = fabsf(d); sl1 += (ad < 1.0f) ? 0.5f * d * d : ad - 0.5f;
                d = pb.w - gb.w; ad = fabsf(d); sl1 += (ad < 1.0f) ? 0.5f * d * d : ad - 0.5f;
                outv = -(sl1 + conf) - 2.0f;
            } else {
                outv = conf;
            }
            g_work[(size_t)b * A_ + anchor] = outv;
        }
        __syncwarp();   // tile fully consumed before its buffer slot is reused
    }
}

// ---------------------------------------------------------------------------
// K2: per-batch block (1024 threads). Fused load/decode/psum/hist1, then
// 2x12-bit radix-select with parallel suffix scans, then top-k sum.
// Last block (atomic ticket) combines the 64 batch results into d_out.
// ---------------------------------------------------------------------------
__device__ __forceinline__ unsigned int f2key(float f)
{
    unsigned int b = __float_as_uint(f);
    return (b & 0x80000000u) ? ~b : (b | 0x80000000u);
}
__device__ __forceinline__ float key2f(unsigned int k)
{
    unsigned int b = (k & 0x80000000u) ? (k ^ 0x80000000u) : ~k;
    return __uint_as_float(b);
}

__global__ void __launch_bounds__(K2T) k2_select(float* __restrict__ out)
{
    __shared__ unsigned int keys[A_];
    __shared__ unsigned int hist[4096];
    __shared__ float s_wf[NWARP];
    __shared__ int   s_wi[NWARP];
    __shared__ int   s_woff[NWARP];
    __shared__ unsigned int s_pref;
    __shared__ int   s_kk;
    __shared__ float s_pos;
    __shared__ int   s_np;
    __shared__ int   s_last;
    __shared__ float s_red64f[B_];
    __shared__ int   s_red64i[B_];

    const int b    = blockIdx.x;
    const int tid  = threadIdx.x;
    const int lane = tid & 31;
    const int wrp  = tid >> 5;

    const unsigned int NEG1_KEY = f2key(-1.0f);

    ((uint4*)hist)[tid] = make_uint4(0, 0, 0, 0);
    __syncthreads();

    float psum = 0.0f;
    int   pcnt = 0;
    for (int i = tid; i < A_; i += K2T) {
        float v = g_work[(size_t)b * A_ + i];
        bool p = v <= -1.5f;
        if (p) { psum += -(v + 2.0f); pcnt++; }
        unsigned int key = p ? NEG1_KEY : f2key(v);
        keys[i] = key;
        atomicAdd(&hist[key >> 20], 1u);
    }
    #pragma unroll
    for (int d = 16; d > 0; d >>= 1) {
        psum += __shfl_down_sync(0xffffffffu, psum, d);
        pcnt += __shfl_down_sync(0xffffffffu, pcnt, d);
    }
    if (lane == 0) { s_wf[wrp] = psum; s_wi[wrp] = pcnt; }
    __syncthreads();
    if (wrp == 0) {
        float f = s_wf[lane];
        int   c = s_wi[lane];
        #pragma unroll
        for (int d = 16; d > 0; d >>= 1) {
            f += __shfl_down_sync(0xffffffffu, f, d);
            c += __shfl_down_sync(0xffffffffu, c, d);
        }
        if (lane == 0) { s_pos = f; s_np = c; }
    }
    __syncthreads();

    const int np = s_np;
    const int k  = min(3 * np, A_ - 1);

    float topk = 0.0f;
    unsigned int pref24 = 0;
    if (k > 0) {
        unsigned int pref12 = 0;
        int kk = k;

        #pragma unroll
        for (int pass = 0; pass < 2; pass++) {
            if (pass == 1) {
                __syncthreads();
                ((uint4*)hist)[tid] = make_uint4(0, 0, 0, 0);
                __syncthreads();
                for (int i = tid; i < A_; i += K2T) {
                    unsigned int key = keys[i];
                    if ((key >> 20) == pref12)
                        atomicAdd(&hist[(key >> 8) & 0xFFFu], 1u);
                }
            }
            __syncthreads();

            uint4 h4 = ((uint4*)hist)[tid];
            int c = (int)(h4.x + h4.y + h4.z + h4.w);
            int incl = c;
            #pragma unroll
            for (int d = 1; d < 32; d <<= 1) {
                int v = __shfl_down_sync(0xffffffffu, incl, d);
                if (lane + d < 32) incl += v;
            }
            if (lane == 0) s_wi[wrp] = incl;
            __syncthreads();
            if (wrp == 0) {
                int v = s_wi[lane];
                int suf = v;
                #pragma unroll
                for (int d = 1; d < 32; d <<= 1) {
                    int u = __shfl_down_sync(0xffffffffu, suf, d);
                    if (lane + d < 32) suf += u;
                }
                s_woff[lane] = suf - v;
            }
            __syncthreads();
            const int above = incl - c + s_woff[wrp];
            if (above < kk && above + c >= kk) {
                unsigned int hv[4] = {h4.x, h4.y, h4.z, h4.w};
                int cum = above;
                #pragma unroll
                for (int j = 3; j >= 0; j--) {
                    int h = (int)hv[j];
                    cum += h;
                    if (cum >= kk) {
                        s_pref = (unsigned int)(tid * 4 + j);
                        s_kk   = kk - (cum - h);
                        break;
                    }
                }
            }
            __syncthreads();
            if (pass == 0) { pref12 = s_pref; }
            else           { pref24 = (pref12 << 12) | s_pref; }
            kk = s_kk;
        }

        const unsigned int T_hi = (pref24 << 8) | 0xFFu;
        float lsum = 0.0f;
        int   lcnt = 0;
        for (int i = tid; i < A_; i += K2T) {
            unsigned int key = keys[i];
            if (key > T_hi) { lsum += key2f(key); lcnt++; }
        }
        #pragma unroll
        for (int d = 16; d > 0; d >>= 1) {
            lsum += __shfl_down_sync(0xffffffffu, lsum, d);
            lcnt += __shfl_down_sync(0xffffffffu, lcnt, d);
        }
        if (lane == 0) { s_wf[wrp] = lsum; s_wi[wrp] = lcnt; }
        __syncthreads();
        if (wrp == 0) {
            float f = s_wf[lane];
            int   c = s_wi[lane];
            #pragma unroll
            for (int d = 16; d > 0; d >>= 1) {
                f += __shfl_down_sync(0xffffffffu, f, d);
                c += __shfl_down_sync(0xffffffffu, c, d);
            }
            if (lane == 0) s_wf[0] = f + (float)(k - c) * key2f(pref24 << 8);
        }
        __syncthreads();
        topk = s_wf[0];
    }

    if (tid == 0) {
        g_batch_loss[b] = s_pos + topk;
        g_batch_np[b]   = np;
        __threadfence();
        int t = atomicAdd(&g_ticket, 1);
        s_last = (t == B_ - 1) ? 1 : 0;
    }
    __syncthreads();

    // Last block combines all 64 batch results (fixed-order reduce).
    if (s_last) {
        if (tid < B_) {
            s_red64f[tid] = *((volatile float*)&g_batch_loss[tid]);
            s_red64i[tid] = max(*((volatile int*)&g_batch_np[tid]), 1);
        }
        __syncthreads();
        for (int off = B_ / 2; off > 0; off >>= 1) {
            if (tid < off) { s_red64f[tid] += s_red64f[tid + off]; s_red64i[tid] += s_red64i[tid + off]; }
            __syncthreads();
        }
        if (tid == 0) {
            out[0] = s_red64f[0] / (float)s_red64i[0];
            g_ticket = 0;   // reset for next graph replay (deterministic)
        }
    }
}

extern "C" void kernel_launch(void* const* d_in, const int* in_sizes, int n_in,
                              void* d_out, int out_size)
{
    const float4* pred_boxes  = (const float4*)d_in[0];  // [B,A,4]
    const float*  pred_scores = (const float*)d_in[1];   // [B,A,C]
    const float4* gt_boxes    = (const float4*)d_in[2];  // [B,G,4]
    const int*    gt_labels   = (const int*)d_in[3];     // [B,G]

    dim3 g1(SPB, B_);
    k1_anchor<<<g1, K1T>>>(pred_boxes, pred_scores, gt_boxes, gt_labels);
    k2_select<<<B_, K2T>>>((float*)d_out);
}

// round 9
// speedup vs baseline: 1.1722x; 1.1722x over previous
#include <cuda_runtime.h>
#include <math.h>
#include <stdint.h>

#define B_ 64
#define A_ 8732
#define G_ 50
#define C_ 81

// ---- K1: block-per-batch strips; warp-private 3-deep cp.async pipelines ----
#define TILE8 8
#define NTB 1092                        // ceil(8732/8) tiles per batch
#define SPB 7                           // strips per batch -> 448 blocks (1 wave @3/SM)
#define TPS 156                         // 1092/7 exactly
#define WPB 8                           // warps per block
#define K1T (WPB * 32)                  // 256
#define NBUF 3
#define ROWF (TILE8 * C_)               // 648 floats (2592 B) per tile buffer
#define BUFB (ROWF * 4)                 // bytes per buffer
#define WARPB (NBUF * BUFB)             // 7776 B per warp
#define DYNSMEM (WPB * WARPB)           // 62208 B

// ---- K2 config ----
#define K2T 1024
#define NWARP (K2T / 32)

// Scratch (no device alloc allowed).
//   negative anchor: v = conf >= 0
//   positive anchor: v = -(sl1 + conf) - 2  (<= -2, disjoint)
__device__ float g_work[B_ * A_];
__device__ float g_batch_loss[B_];
__device__ int   g_batch_np[B_];
__device__ int   g_ticket = 0;

__device__ __forceinline__ float fast_ex2(float x)
{
    float r;
    asm("ex2.approx.ftz.f32 %0, %1;" : "=f"(r) : "f"(x));
    return r;
}
__device__ __forceinline__ uint32_t smem_u32(const void* p)
{
    uint32_t a;
    asm("{ .reg .u64 t; cvta.to.shared.u64 t, %1; cvt.u32.u64 %0, t; }" : "=r"(a) : "l"(p));
    return a;
}
__device__ __forceinline__ void cp16(uint32_t dst, const void* src)
{
    asm volatile("cp.async.cg.shared.global [%0], [%1], 16;" :: "r"(dst), "l"(src));
}

// ---------------------------------------------------------------------------
// K1: blockIdx.y = batch, blockIdx.x = strip. GT boxes/areas/labels staged
// once per block. Each warp owns a 3-deep cp.async pipeline of 8-anchor tiles
// (2 tiles in flight hides loaded DRAM latency). Four lanes serve one anchor:
// quarter q splits the 50 GTs (13/13/12/12) and 81 classes (21/20/20/20);
// partials merged via two shfl_xor levels (lower GT index wins ties).
// ---------------------------------------------------------------------------
__global__ void __launch_bounds__(K1T, 3) k1_anchor(
    const float4* __restrict__ pred_boxes,   // [B, A, 4]
    const float*  __restrict__ pred_scores,  // [B, A, C]
    const float4* __restrict__ gt_boxes,     // [B, G, 4]
    const int*    __restrict__ gt_labels)    // [B, G]
{
    extern __shared__ __align__(16) float dyn[];          // WPB * NBUF * ROWF
    __shared__ __align__(16) float4 s_gtb[G_];
    __shared__ float s_gta[G_];
    __shared__ int   s_gl[G_];

    const int tid  = threadIdx.x;
    const int lane = tid & 31;
    const int wid  = tid >> 5;
    const int al   = lane & 7;      // anchor slot in tile
    const int q    = lane >> 3;     // quarter 0..3

    const int b = blockIdx.y;

    if (tid < G_) {
        float4 g = gt_boxes[b * G_ + tid];
        s_gtb[tid] = g;
        s_gta[tid] = (g.z - g.x) * (g.w - g.y);
        s_gl[tid]  = gt_labels[b * G_ + tid];
    }
    __syncthreads();

    const int gbase = (q < 2) ? q * 13 : 26 + (q - 2) * 12;   // 0,13,26,38
    const int gext  = (q < 2);                                // 13th GT
    const int cbase = (q == 0) ? 0 : 21 + (q - 1) * 20;       // 0,21,41,61

    const int strip_lo = blockIdx.x * TPS;
    const int strip_hi = min(strip_lo + TPS, NTB);

    const uint32_t wbase = smem_u32(dyn) + wid * WARPB;
    const float*   wrow  = dyn + wid * (NBUF * ROWF);
    const float L2E = 1.4426950408889634f;
    const float* sc_base = pred_scores + (size_t)b * A_ * C_;

    auto prefetch = [&](int ti, int sel) {
        const int nA = (ti == NTB - 1) ? (A_ - (NTB - 1) * TILE8) : TILE8;
        const int n4 = (nA * C_) >> 2;     // 162 or 81
        const float4* src = (const float4*)(sc_base + (size_t)ti * (TILE8 * C_));
        const uint32_t dst = wbase + sel * BUFB;
        #pragma unroll
        for (int i = lane; i < ROWF / 4; i += 32)
            if (i < n4) cp16(dst + i * 16, src + i);
    };

    const int t0 = strip_lo + wid;
    // prologue: fill 2 pipeline stages
    #pragma unroll
    for (int j = 0; j < NBUF - 1; j++) {
        int tp = t0 + j * WPB;
        if (tp < strip_hi) prefetch(tp, j);
        asm volatile("cp.async.commit_group;");
    }

    int sel = 0, psel = NBUF - 1;
    for (int ti = t0; ti < strip_hi; ti += WPB) {
        const int a0 = ti * TILE8;
        const int nA = min(TILE8, A_ - a0);
        const int ac = min(al, nA - 1);          // clamped, lanes stay convergent
        const int anchor = a0 + ac;

        // anchor box load overlaps the pipeline wait
        const float4 pb = __ldg(pred_boxes + (size_t)b * A_ + anchor);

        const int tp = ti + (NBUF - 1) * WPB;
        if (tp < strip_hi) prefetch(tp, psel);
        asm volatile("cp.async.commit_group;");
        asm volatile("cp.async.wait_group 2;");   // current tile's group done
        __syncwarp();

        const float area_a = (pb.z - pb.x) * (pb.w - pb.y);

        // ---- IoU argmax over this quarter's 12-13 GTs (division-free) ----
        float bi = -1.0f, bu = 1.0f;
        int bidx = gbase;
        #pragma unroll
        for (int g = 0; g < 12; g++) {
            float4 gb = s_gtb[gbase + g];
            float iw = fmaxf(fminf(pb.z, gb.z) - fmaxf(pb.x, gb.x), 0.0f);
            float ih = fminf(pb.w, gb.w) - fmaxf(pb.y, gb.y);
            float inter = iw * ih;
            float un = (area_a + s_gta[gbase + g]) - inter;   // > 0 always
            if (inter * bu > bi * un) { bi = inter; bu = un; bidx = gbase + g; }
        }
        if (gext) {
            float4 gb = s_gtb[gbase + 12];
            float iw = fmaxf(fminf(pb.z, gb.z) - fmaxf(pb.x, gb.x), 0.0f);
            float ih = fminf(pb.w, gb.w) - fmaxf(pb.y, gb.y);
            float inter = iw * ih;
            float un = (area_a + s_gta[gbase + 12]) - inter;
            if (inter * bu > bi * un) { bi = inter; bu = un; bidx = gbase + 12; }
        }
        // merge quarters (lower index wins ties -> argmax-first semantics)
        #pragma unroll
        for (int off = 8; off <= 16; off <<= 1) {
            float obi = __shfl_xor_sync(0xffffffffu, bi, off);
            float obu = __shfl_xor_sync(0xffffffffu, bu, off);
            int   obx = __shfl_xor_sync(0xffffffffu, bidx, off);
            float lhs = obi * bu, rhs = bi * obu;
            if (lhs > rhs || (lhs == rhs && obx < bidx)) { bi = obi; bu = obu; bidx = obx; }
        }
        const bool pos = bi > 0.5f * bu;
        const int  tl  = pos ? s_gl[bidx] : 0;

        // ---- softmax quarter: 20(+1) classes from this warp's smem tile ----
        const float* row = wrow + sel * ROWF + ac * C_;
        float s0 = 0.0f, s1 = 0.0f;
        #pragma unroll
        for (int j = 0; j < 20; j += 2) {
            s0 += fast_ex2(row[cbase + j]     * L2E);
            s1 += fast_ex2(row[cbase + j + 1] * L2E);
        }
        float s = s0 + s1;
        if (q == 0) s += fast_ex2(row[20] * L2E);
        s += __shfl_xor_sync(0xffffffffu, s, 8);
        s += __shfl_xor_sync(0xffffffffu, s, 16);
        const float conf = __logf(s) - row[tl];

        // ---- emit (quarter 0, valid lanes only) ----
        if (q == 0 && al < nA) {
            float outv;
            if (tl > 0) {
                float4 gb = s_gtb[bidx];
                float sl1 = 0.0f, d, ad;
                d = pb.x - gb.x; ad = fabsf(d); sl1 += (ad < 1.0f) ? 0.5f * d * d : ad - 0.5f;
                d = pb.y - gb.y; ad = fabsf(d); sl1 += (ad < 1.0f) ? 0.5f * d * d : ad - 0.5f;
                d = pb.z - gb.z; ad = fabsf(d); sl1 += (ad < 1.0f) ? 0.5f * d * d : ad - 0.5f;
                d = pb.w - gb.w; ad = fabsf(d); sl1 += (ad < 1.0f) ? 0.5f * d * d : ad - 0.5f;
                outv = -(sl1 + conf) - 2.0f;
            } else {
                outv = conf;
            }
            g_work[(size_t)b * A_ + anchor] = outv;
        }
        __syncwarp();   // tile fully consumed before its buffer slot is reused

        sel  = (sel  == NBUF - 1) ? 0 : sel + 1;
        psel = (psel == NBUF - 1) ? 0 : psel + 1;
    }
}

// ---------------------------------------------------------------------------
// K2: per-batch block (1024 threads). Fused load/decode/psum/hist1, then
// 2x12-bit radix-select with parallel suffix scans, then top-k sum.
// Last block (atomic ticket) combines the 64 batch results into d_out.
// ---------------------------------------------------------------------------
__device__ __forceinline__ unsigned int f2key(float f)
{
    unsigned int b = __float_as_uint(f);
    return (b & 0x80000000u) ? ~b : (b | 0x80000000u);
}
__device__ __forceinline__ float key2f(unsigned int k)
{
    unsigned int b = (k & 0x80000000u) ? (k ^ 0x80000000u) : ~k;
    return __uint_as_float(b);
}

__global__ void __launch_bounds__(K2T) k2_select(float* __restrict__ out)
{
    __shared__ unsigned int keys[A_];
    __shared__ unsigned int hist[4096];
    __shared__ float s_wf[NWARP];
    __shared__ int   s_wi[NWARP];
    __shared__ int   s_woff[NWARP];
    __shared__ unsigned int s_pref;
    __shared__ int   s_kk;
    __shared__ float s_pos;
    __shared__ int   s_np;
    __shared__ int   s_last;
    __shared__ float s_red64f[B_];
    __shared__ int   s_red64i[B_];

    const int b    = blockIdx.x;
    const int tid  = threadIdx.x;
    const int lane = tid & 31;
    const int wrp  = tid >> 5;

    const unsigned int NEG1_KEY = f2key(-1.0f);

    ((uint4*)hist)[tid] = make_uint4(0, 0, 0, 0);
    __syncthreads();

    float psum = 0.0f;
    int   pcnt = 0;
    for (int i = tid; i < A_; i += K2T) {
        float v = g_work[(size_t)b * A_ + i];
        bool p = v <= -1.5f;
        if (p) { psum += -(v + 2.0f); pcnt++; }
        unsigned int key = p ? NEG1_KEY : f2key(v);
        keys[i] = key;
        atomicAdd(&hist[key >> 20], 1u);
    }
    #pragma unroll
    for (int d = 16; d > 0; d >>= 1) {
        psum += __shfl_down_sync(0xffffffffu, psum, d);
        pcnt += __shfl_down_sync(0xffffffffu, pcnt, d);
    }
    if (lane == 0) { s_wf[wrp] = psum; s_wi[wrp] = pcnt; }
    __syncthreads();
    if (wrp == 0) {
        float f = s_wf[lane];
        int   c = s_wi[lane];
        #pragma unroll
        for (int d = 16; d > 0; d >>= 1) {
            f += __shfl_down_sync(0xffffffffu, f, d);
            c += __shfl_down_sync(0xffffffffu, c, d);
        }
        if (lane == 0) { s_pos = f; s_np = c; }
    }
    __syncthreads();

    const int np = s_np;
    const int k  = min(3 * np, A_ - 1);

    float topk = 0.0f;
    unsigned int pref24 = 0;
    if (k > 0) {
        unsigned int pref12 = 0;
        int kk = k;

        #pragma unroll
        for (int pass = 0; pass < 2; pass++) {
            if (pass == 1) {
                __syncthreads();
                ((uint4*)hist)[tid] = make_uint4(0, 0, 0, 0);
                __syncthreads();
                for (int i = tid; i < A_; i += K2T) {
                    unsigned int key = keys[i];
                    if ((key >> 20) == pref12)
                        atomicAdd(&hist[(key >> 8) & 0xFFFu], 1u);
                }
            }
            __syncthreads();

            uint4 h4 = ((uint4*)hist)[tid];
            int c = (int)(h4.x + h4.y + h4.z + h4.w);
            int incl = c;
            #pragma unroll
            for (int d = 1; d < 32; d <<= 1) {
                int v = __shfl_down_sync(0xffffffffu, incl, d);
                if (lane + d < 32) incl += v;
            }
            if (lane == 0) s_wi[wrp] = incl;
            __syncthreads();
            if (wrp == 0) {
                int v = s_wi[lane];
                int suf = v;
                #pragma unroll
                for (int d = 1; d < 32; d <<= 1) {
                    int u = __shfl_down_sync(0xffffffffu, suf, d);
                    if (lane + d < 32) suf += u;
                }
                s_woff[lane] = suf - v;
            }
            __syncthreads();
            const int above = incl - c + s_woff[wrp];
            if (above < kk && above + c >= kk) {
                unsigned int hv[4] = {h4.x, h4.y, h4.z, h4.w};
                int cum = above;
                #pragma unroll
                for (int j = 3; j >= 0; j--) {
                    int h = (int)hv[j];
                    cum += h;
                    if (cum >= kk) {
                        s_pref = (unsigned int)(tid * 4 + j);
                        s_kk   = kk - (cum - h);
                        break;
                    }
                }
            }
            __syncthreads();
            if (pass == 0) { pref12 = s_pref; }
            else           { pref24 = (pref12 << 12) | s_pref; }
            kk = s_kk;
        }

        const unsigned int T_hi = (pref24 << 8) | 0xFFu;
        float lsum = 0.0f;
        int   lcnt = 0;
        for (int i = tid; i < A_; i += K2T) {
            unsigned int key = keys[i];
            if (key > T_hi) { lsum += key2f(key); lcnt++; }
        }
        #pragma unroll
        for (int d = 16; d > 0; d >>= 1) {
            lsum += __shfl_down_sync(0xffffffffu, lsum, d);
            lcnt += __shfl_down_sync(0xffffffffu, lcnt, d);
        }
        if (lane == 0) { s_wf[wrp] = lsum; s_wi[wrp] = lcnt; }
        __syncthreads();
        if (wrp == 0) {
            float f = s_wf[lane];
            int   c = s_wi[lane];
            #pragma unroll
            for (int d = 16; d > 0; d >>= 1) {
                f += __shfl_down_sync(0xffffffffu, f, d);
                c += __shfl_down_sync(0xffffffffu, c, d);
            }
            if (lane == 0) s_wf[0] = f + (float)(k - c) * key2f(pref24 << 8);
        }
        __syncthreads();
        topk = s_wf[0];
    }

    if (tid == 0) {
        g_batch_loss[b] = s_pos + topk;
        g_batch_np[b]   = np;
        __threadfence();
        int t = atomicAdd(&g_ticket, 1);
        s_last = (t == B_ - 1) ? 1 : 0;
    }
    __syncthreads();

    // Last block combines all 64 batch results (fixed-order reduce).
    if (s_last) {
        if (tid < B_) {
            s_red64f[tid] = *((volatile float*)&g_batch_loss[tid]);
            s_red64i[tid] = max(*((volatile int*)&g_batch_np[tid]), 1);
        }
        __syncthreads();
        for (int off = B_ / 2; off > 0; off >>= 1) {
            if (tid < off) { s_red64f[tid] += s_red64f[tid + off]; s_red64i[tid] += s_red64i[tid + off]; }
            __syncthreads();
        }
        if (tid == 0) {
            out[0] = s_red64f[0] / (float)s_red64i[0];
            g_ticket = 0;   // reset for next graph replay (deterministic)
        }
    }
}

extern "C" void kernel_launch(void* const* d_in, const int* in_sizes, int n_in,
                              void* d_out, int out_size)
{
    const float4* pred_boxes  = (const float4*)d_in[0];  // [B,A,4]
    const float*  pred_scores = (const float*)d_in[1];   // [B,A,C]
    const float4* gt_boxes    = (const float4*)d_in[2];  // [B,G,4]
    const int*    gt_labels   = (const int*)d_in[3];     // [B,G]

    cudaFuncSetAttribute(k1_anchor, cudaFuncAttributeMaxDynamicSharedMemorySize,
                         DYNSMEM);
    dim3 g1(SPB, B_);
    k1_anchor<<<g1, K1T, DYNSMEM>>>(pred_boxes, pred_scores, gt_boxes, gt_labels);
    k2_select<<<B_, K2T>>>((float*)d_out);
}